// round 3
// baseline (speedup 1.0000x reference)
#include <cuda_runtime.h>

#define NPB 15   // prob bins
#define NC  8    // classes
#define NNB 9    // neighbor bins
#define HH  512
#define WW  512
#define SOUT 30          // output columns per warp strip (32 lanes - 2 halo)
#define RCH  36          // rows per warp chunk (multiple of 3)
#define NSTRIP 18        // ceil(512/30)
#define NCHUNK 15        // ceil(512/36)
#define NB 16            // batch
#define WPB 8            // warps per block
#define NTHREADS 256

__device__ __forceinline__ void prob_row(float p[NC], const float* lb, int y,
                                         long plane, bool xload)
{
    if ((unsigned)y < HH) {             // warp-uniform branch
        float r[NC];
        const float* q = lb + (long)y * WW;
#pragma unroll
        for (int c = 0; c < NC; c++) r[c] = q[c * plane];
        float m01 = fmaxf(r[0], r[1]), m23 = fmaxf(r[2], r[3]);
        float m45 = fmaxf(r[4], r[5]), m67 = fmaxf(r[6], r[7]);
        float m = fmaxf(fmaxf(m01, m23), fmaxf(m45, m67));
        float e[NC];
#pragma unroll
        for (int c = 0; c < NC; c++) e[c] = __expf(r[c] - m);
        float s = ((e[0] + e[1]) + (e[2] + e[3])) + ((e[4] + e[5]) + (e[6] + e[7]));
        float inv = __frcp_rn(s);
#pragma unroll
        for (int c = 0; c < NC; c++) p[c] = xload ? e[c] * inv : 0.f;
    } else {
#pragma unroll
        for (int c = 0; c < NC; c++) p[c] = 0.f;
    }
}

__device__ __forceinline__ void process_row(
    const float pa[NC], const float pb[NC], const float pc[NC],
    int y, bool xout, float* ob, long plane, const float* s_vf)
{
    if ((unsigned)y >= HH) return;      // warp-uniform
    float nsum[NC];
#pragma unroll
    for (int c = 0; c < NC; c++) {
        float cs = pa[c] + pb[c] + pc[c];                     // vertical 3-sum
        float lft = __shfl_up_sync(0xffffffffu, cs, 1);       // lane-1 colsum
        float rgt = __shfl_down_sync(0xffffffffu, cs, 1);     // lane+1 colsum
        nsum[c] = lft + cs + rgt;                             // horizontal 3-sum
    }
    float f[NC];
    bool need = false;
#pragma unroll
    for (int c = 0; c < NC; c++) {
        // fast path: floor(RN(RN(s/9)*9)) == floor(s) unless s within ~2.5ulp
        // of an integer; 1e-5 window triggers the exact double-rounded path.
        float s9 = nsum[c];
        int ib = (int)s9;                 // trunc == floor (s9 >= 0)
        float fr = s9 - (float)ib;
        need |= (fr < 1e-5f) || (fr > 0.99999f);
        int lbn = min(ib, NNB - 1);
        int pbn = min((int)(pb[c] * 15.0f), NPB - 1);
        f[c] = s_vf[(c * NNB + lbn) * NPB + pbn];
    }
    if (need) {                           // rare: replicate reference rounding exactly
#pragma unroll
        for (int c = 0; c < NC; c++) {
            int lbn = (int)floorf(__fmul_rn(__fdiv_rn(nsum[c], 9.0f), 9.0f));
            lbn = max(0, min(lbn, NNB - 1));
            int pbn = min((int)(pb[c] * 15.0f), NPB - 1);
            f[c] = s_vf[(c * NNB + lbn) * NPB + pbn];
        }
    }
    float s = ((f[0] + f[1]) + (f[2] + f[3])) + ((f[4] + f[5]) + (f[6] + f[7]));
    if (s == 0.f) s = 1.f;
    float inv = __frcp_rn(s);
    if (xout) {
        float* o = ob + (long)y * WW;
#pragma unroll
        for (int c = 0; c < NC; c++) o[c * plane] = f[c] * inv;
    }
}

__global__ __launch_bounds__(NTHREADS, 4) void nectar_kernel(
    const float* __restrict__ logits,
    const float* __restrict__ vf,
    float* __restrict__ out)
{
    __shared__ float s_vf[NC * NNB * NPB];
    for (int i = threadIdx.x; i < NC * NNB * NPB; i += NTHREADS) s_vf[i] = vf[i];
    __syncthreads();

    const int lane = threadIdx.x & 31;
    const int wid  = blockIdx.x * WPB + (threadIdx.x >> 5);
    const int b    = wid / (NSTRIP * NCHUNK);
    const int rem  = wid - b * (NSTRIP * NCHUNK);
    const int chunk = rem / NSTRIP;
    const int strip = rem - chunk * NSTRIP;

    const int x = strip * SOUT + lane - 1;           // lane 0 / 31 are halo
    const bool xload = (x >= 0) && (x < WW);
    const bool xout  = (lane >= 1) && (lane <= SOUT) && (x < WW);
    const int  xc = min(max(x, 0), WW - 1);          // clamp: loads always legal
    const int  y0 = chunk * RCH;

    const long plane = (long)HH * WW;
    const float* lb = logits + (long)b * NC * plane + xc;
    float* ob       = out    + (long)b * NC * plane + xc;   // x==xc when xout

    float pa[NC], pb_[NC], pc[NC];
    prob_row(pa,  lb, y0 - 1, plane, xload);
    prob_row(pb_, lb, y0,     plane, xload);

    int y = y0;
#pragma unroll 1
    for (int i = 0; i < RCH / 3; i++) {              // role-rotating triple
        prob_row(pc,  lb, y + 1, plane, xload);
        process_row(pa, pb_, pc, y,     xout, ob, plane, s_vf);
        prob_row(pa,  lb, y + 2, plane, xload);
        process_row(pb_, pc, pa, y + 1, xout, ob, plane, s_vf);
        prob_row(pb_, lb, y + 3, plane, xload);
        process_row(pc, pa, pb_, y + 2, xout, ob, plane, s_vf);
        y += 3;
    }
}

extern "C" void kernel_launch(void* const* d_in, const int* in_sizes, int n_in,
                              void* d_out, int out_size)
{
    const float* logits = (const float*)d_in[0];
    const float* vf     = (const float*)d_in[1];
    float* out          = (float*)d_out;

    // 16 batches x 15 chunks x 18 strips = 4320 warp-tasks -> 540 blocks of 8 warps
    dim3 grid(NB * NCHUNK * NSTRIP / WPB);
    nectar_kernel<<<grid, NTHREADS>>>(logits, vf, out);
}

// round 4
// speedup vs baseline: 1.2550x; 1.2550x over previous
#include <cuda_runtime.h>

#define NPB 15   // prob bins
#define NC  8    // classes
#define NNB 9    // neighbor bins (3x3)
#define HH  512
#define WW  512
#define TX  32
#define TY  16
#define NTHREADS (TX*TY)

__global__ __launch_bounds__(NTHREADS, 4) void nectar_kernel(
    const float* __restrict__ logits,
    const float* __restrict__ vf,
    float* __restrict__ out)
{
    // channel-major smem: lane-consecutive spatial index -> conflict-free
    __shared__ float s_probs[NC][TY + 2][TX + 2];
    __shared__ float s_col[NC][TY][TX + 2];
    __shared__ float s_vf[NC * NNB * NPB];

    const int t  = threadIdx.y * TX + threadIdx.x;
    const int b  = blockIdx.z;
    const int bx = blockIdx.x * TX;
    const int by = blockIdx.y * TY;

    // stage calibration table
    for (int i = t; i < NC * NNB * NPB; i += NTHREADS) s_vf[i] = vf[i];

    const long plane = (long)HH * WW;
    const float* lbase = logits + (long)b * NC * plane;

    // Stage 1: halo softmax -> smem probs (0 outside image, matching SAME/zero pad)
    for (int i = t; i < (TY + 2) * (TX + 2); i += NTHREADS) {
        const int hy = i / (TX + 2);
        const int hx = i % (TX + 2);
        const int gy = by + hy - 1;
        const int gx = bx + hx - 1;
        if (gy >= 0 && gy < HH && gx >= 0 && gx < WW) {
            float v[NC];
            const float* p0 = lbase + (long)gy * WW + gx;
#pragma unroll
            for (int c = 0; c < NC; c++) v[c] = p0[c * plane];
            float m01 = fmaxf(v[0], v[1]), m23 = fmaxf(v[2], v[3]);
            float m45 = fmaxf(v[4], v[5]), m67 = fmaxf(v[6], v[7]);
            const float m = fmaxf(fmaxf(m01, m23), fmaxf(m45, m67));
#pragma unroll
            for (int c = 0; c < NC; c++) v[c] = __expf(v[c] - m);
            const float s = ((v[0] + v[1]) + (v[2] + v[3]))
                          + ((v[4] + v[5]) + (v[6] + v[7]));
            const float inv = __frcp_rn(s);
#pragma unroll
            for (int c = 0; c < NC; c++)
                s_probs[c][hy][hx] = v[c] * inv;
        } else {
#pragma unroll
            for (int c = 0; c < NC; c++)
                s_probs[c][hy][hx] = 0.f;
        }
    }
    __syncthreads();

    // Stage 2: vertical 3-sum (separable box filter, pass 1)
    for (int i = t; i < TY * (TX + 2); i += NTHREADS) {
        const int cy = i / (TX + 2);
        const int cx = i % (TX + 2);
#pragma unroll
        for (int c = 0; c < NC; c++)
            s_col[c][cy][cx] = s_probs[c][cy][cx]
                             + s_probs[c][cy + 1][cx]
                             + s_probs[c][cy + 2][cx];
    }
    __syncthreads();

    // Stage 3: horizontal 3-sum, binning, gather, normalize, store
    const int tx = threadIdx.x;
    const int ty = threadIdx.y;
    const int gx = bx + tx;
    const int gy = by + ty;

    float nsum[NC], f[NC];
    bool need = false;
#pragma unroll
    for (int c = 0; c < NC; c++) {
        const float p = s_probs[c][ty + 1][tx + 1];
        const float s9 = s_col[c][ty][tx]
                       + s_col[c][ty][tx + 1]
                       + s_col[c][ty][tx + 2];
        nsum[c] = s9;
        // fast path: floor(RN(RN(s/9)*9)) == floor(s) unless s is within
        // ~2.5 ulp of an integer; a 1e-5 window guards the rare exact path.
        const int ib = (int)s9;             // trunc == floor (s9 >= 0)
        const float fr = s9 - (float)ib;
        need |= (fr < 1e-5f) | (fr > 0.99999f);
        const int lbn = min(ib, NNB - 1);
        const int pbn = min((int)(p * 15.0f), NPB - 1);   // p >= 0
        f[c] = s_vf[(c * NNB + lbn) * NPB + pbn];
    }
    if (need) {   // rare: replicate the reference's double rounding exactly
#pragma unroll
        for (int c = 0; c < NC; c++) {
            const float p = s_probs[c][ty + 1][tx + 1];
            int lbn = (int)floorf(__fmul_rn(__fdiv_rn(nsum[c], 9.0f), 9.0f));
            lbn = max(0, min(lbn, NNB - 1));
            const int pbn = min((int)(p * 15.0f), NPB - 1);
            f[c] = s_vf[(c * NNB + lbn) * NPB + pbn];
        }
    }
    float s = ((f[0] + f[1]) + (f[2] + f[3])) + ((f[4] + f[5]) + (f[6] + f[7]));
    if (s == 0.f) s = 1.f;
    // continuous path: reciprocal-multiply, no binning downstream
    const float invs = __frcp_rn(s);

    float* obase = out + (long)b * NC * plane + (long)gy * WW + gx;
#pragma unroll
    for (int c = 0; c < NC; c++)
        obase[c * plane] = f[c] * invs;
}

extern "C" void kernel_launch(void* const* d_in, const int* in_sizes, int n_in,
                              void* d_out, int out_size)
{
    const float* logits = (const float*)d_in[0];
    const float* vf     = (const float*)d_in[1];
    float* out          = (float*)d_out;

    dim3 block(TX, TY);
    dim3 grid(WW / TX, HH / TY, 16 /*B*/);
    nectar_kernel<<<grid, block>>>(logits, vf, out);
}